// round 8
// baseline (speedup 1.0000x reference)
#include <cuda_runtime.h>
#include <cuda_bf16.h>
#include <math.h>
#include <cstdint>

// ---------------------------------------------------------------------------
// Problem constants (fixed by setup_inputs)
// ---------------------------------------------------------------------------
#define Bb    2
#define Cd    768
#define Lh    4096            // H*W
#define Mrows (Bb*Lh)         // 8192
#define TWOD  1536
#define DBLS  64              // padded dt_raw|B|C row stride (56 -> 64)
#define RK    48
#define NS    4
#define NCh   64              // scan chunks per batch
#define LCh   64              // chunk length  (NCh*LCh == Lh)

// ---------------------------------------------------------------------------
// Static device scratch (no cudaMalloc allowed)
// ---------------------------------------------------------------------------
__device__ float          g_xt  [2][Mrows*Cd];     // residual (B,L,C) fp32
__device__ __nv_bfloat16  g_xnb [2][Mrows*Cd];     // layernormed x, bf16
__device__ float          g_mean[2][Mrows];
__device__ float          g_rstd[2][Mrows];
__device__ __nv_bfloat16  g_uzb [2][Mrows*TWOD];   // in_proj output bf16
__device__ __nv_bfloat16  g_ub  [2][Mrows*Cd];     // conv+silu bf16
__device__ float          g_dbl [2][Mrows*DBLS];   // dt_raw | B | C (stride 64)
__device__ __nv_bfloat16  g_dtrb[2][Mrows*64];     // dt_raw bf16, K padded to 64
__device__ float          g_dt  [2][Mrows*Cd];     // softplus dt (fp32: scan-critical)
__device__ __nv_bfloat16  g_yzb [2][Mrows*Cd];     // y * silu(z) bf16
__device__ float          g_P   [2][Bb*Cd*NCh*NS];
__device__ float          g_Hc  [2][Bb*Cd*NCh*NS];
// transposed bf16 weights: Wt[n][k], zero padded
__device__ __nv_bfloat16  g_wint [2][TWOD*Cd];     // in_proj  [1536][768]
__device__ __nv_bfloat16  g_woutt[2][Cd*Cd];       // out_proj [768][768]
__device__ __nv_bfloat16  g_wxpt [2][64*Cd];       // x_proj   [64][768] (56 used)
__device__ __nv_bfloat16  g_wdtt [2][Cd*64];       // dt_proj  [768][64] (48 used)

// ---------------------------------------------------------------------------
// PTX helpers (sm_80-era: cp.async + ldmatrix + mma.sync -- works on sm_103)
// ---------------------------------------------------------------------------
__device__ __forceinline__ uint32_t smem_u32(const void* p) {
    uint32_t a;
    asm("{ .reg .u64 t; cvta.to.shared.u64 t, %1; cvt.u32.u64 %0, t; }"
        : "=r"(a) : "l"(p));
    return a;
}
__device__ __forceinline__ void cpa16(uint32_t s, const void* g) {
    asm volatile("cp.async.cg.shared.global [%0], [%1], 16;" :: "r"(s), "l"(g));
}
__device__ __forceinline__ void cpa_commit() {
    asm volatile("cp.async.commit_group;" ::: "memory");
}
__device__ __forceinline__ void cpa_wait1() {
    asm volatile("cp.async.wait_group 1;" ::: "memory");
}
__device__ __forceinline__ void cpa_wait0() {
    asm volatile("cp.async.wait_group 0;" ::: "memory");
}
__device__ __forceinline__ void ldsm4(uint32_t& r0, uint32_t& r1,
                                      uint32_t& r2, uint32_t& r3, uint32_t a) {
    asm volatile("ldmatrix.sync.aligned.m8n8.x4.shared.b16 {%0,%1,%2,%3}, [%4];"
                 : "=r"(r0), "=r"(r1), "=r"(r2), "=r"(r3) : "r"(a));
}
__device__ __forceinline__ void mma16816(float* d, const uint32_t* a,
                                         uint32_t b0, uint32_t b1) {
    asm volatile(
        "mma.sync.aligned.m16n8k16.row.col.f32.bf16.bf16.f32 "
        "{%0,%1,%2,%3}, {%4,%5,%6,%7}, {%8,%9}, {%0,%1,%2,%3};"
        : "+f"(d[0]), "+f"(d[1]), "+f"(d[2]), "+f"(d[3])
        : "r"(a[0]), "r"(a[1]), "r"(a[2]), "r"(a[3]), "r"(b0), "r"(b1));
}

// ---------------------------------------------------------------------------
// LayerNorm stats, both streams in one launch (blockIdx.y = stream)
// ---------------------------------------------------------------------------
__global__ void ln_stats_b(const float* __restrict__ x0,
                           const float* __restrict__ x1,
                           float* __restrict__ mean, float* __restrict__ rstd)
{
    int r = blockIdx.x * blockDim.x + threadIdx.x;
    if (r >= Mrows) return;
    const int s = blockIdx.y;
    const float* x = s ? x1 : x0;
    mean += s * Mrows; rstd += s * Mrows;
    int b = r / Lh, l = r % Lh;
    const float* xp = x + (size_t)b * Cd * Lh + l;
    float sum = 0.f, sum2 = 0.f;
#pragma unroll 8
    for (int c = 0; c < Cd; c++) {
        float v = __ldg(xp + (size_t)c * Lh);
        sum += v;
        sum2 = fmaf(v, v, sum2);
    }
    float m   = sum * (1.f / Cd);
    float var = sum2 * (1.f / Cd) - m * m;
    mean[r] = m;
    rstd[r] = rsqrtf(var + 1e-5f);
}

// ---------------------------------------------------------------------------
// Transpose BCHW -> (B,L,C), both streams (blockIdx.z = s*Bb + b)
// ---------------------------------------------------------------------------
struct TnArgs { const float* x[2]; const float* g[2]; const float* lb[2]; };

__global__ void tn_b(TnArgs a,
                     const float* __restrict__ mean, const float* __restrict__ rstd,
                     float* __restrict__ xt, __nv_bfloat16* __restrict__ xn)
{
    __shared__ float t[32][33];
    const int s = blockIdx.z >> 1;
    const int b = blockIdx.z & 1;
    const float* x = a.x[s];
    const float* g = a.g[s];
    const float* lb = a.lb[s];
    mean += s * Mrows; rstd += s * Mrows;
    xt += (size_t)s * Mrows * Cd;
    xn += (size_t)s * Mrows * Cd;

    int c0 = blockIdx.y * 32;
    int l0 = blockIdx.x * 32;
#pragma unroll
    for (int i = 0; i < 4; i++) {
        int c = c0 + threadIdx.y + i * 8;
        t[threadIdx.y + i * 8][threadIdx.x] =
            x[((size_t)b * Cd + c) * Lh + l0 + threadIdx.x];
    }
    __syncthreads();
#pragma unroll
    for (int i = 0; i < 4; i++) {
        int l = l0 + threadIdx.y + i * 8;
        int c = c0 + threadIdx.x;
        int r = b * Lh + l;
        float v = t[threadIdx.x][threadIdx.y + i * 8];
        size_t o = (size_t)r * Cd + c;
        xt[o] = v;
        xn[o] = __float2bfloat16((v - mean[r]) * rstd[r] * g[c] + lb[c]);
    }
}

// ---------------------------------------------------------------------------
// Batched weight transpose + fp32->bf16 + zero pad (8 matrices in one launch)
// ---------------------------------------------------------------------------
struct WtArgs { const float* W[8]; __nv_bfloat16* Wt[8]; };

__global__ void wt_all_k(WtArgs a)
{
    const int id = blockIdx.z;
    const int m  = id & 3;      // 0=in, 1=out, 2=xp, 3=dt
    const int Ks[4]  = {Cd, Cd, Cd, RK};
    const int Ns[4]  = {TWOD, Cd, 56, Cd};
    const int Kps[4] = {Cd, Cd, Cd, 64};
    const int Nps[4] = {TWOD, Cd, 64, Cd};
    const int bxs[4] = {Cd/32, Cd/32, Cd/32, 2};
    const int bys[4] = {TWOD/32, Cd/32, 2, Cd/32};
    if ((int)blockIdx.x >= bxs[m] || (int)blockIdx.y >= bys[m]) return;
    const int K = Ks[m], N = Ns[m], Kpad = Kps[m], Npad = Nps[m];
    const float* W = a.W[id];
    __nv_bfloat16* Wt = a.Wt[id];

    __shared__ float t[32][33];
    int k0 = blockIdx.x * 32, n0 = blockIdx.y * 32;
#pragma unroll
    for (int i = 0; i < 4; i++) {
        int k = k0 + threadIdx.y + i * 8;
        int n = n0 + threadIdx.x;
        t[threadIdx.y + i * 8][threadIdx.x] =
            (k < K && n < N) ? W[(size_t)k * N + n] : 0.f;
    }
    __syncthreads();
#pragma unroll
    for (int i = 0; i < 4; i++) {
        int n = n0 + threadIdx.y + i * 8;
        int k = k0 + threadIdx.x;
        if (n < Npad && k < Kpad)
            Wt[(size_t)n * Kpad + k] = __float2bfloat16(t[threadIdx.x][threadIdx.y + i * 8]);
    }
}

// ---------------------------------------------------------------------------
// HMMA bf16 GEMM: C[M,N] = A[M,K] @ Wt[N,K]^T, fp32 accumulate.
//   CTA tile MT x NT, BK=64, 256 threads = 8 warps, 3-stage cp.async pipeline.
//   Inner loop: flattened (ks,nj) steps with one-step REGISTER lookahead --
//   ldsm for step t+1 issued before MMAs of step t, hiding LDS latency.
//   EPI 0: fp32 | 1: fp32 + bf16 dtrb copy (stride 64, zero c>=48)
//   EPI 2: softplus(v+aux[c]) fp32 | 3: v+aux[r*ldc+c] fp32 | 4: bf16 only
// ---------------------------------------------------------------------------
struct GemmAux { const float* a[2]; __nv_bfloat16* bf[2]; };

template<int MT, int NT, int EPI>
__global__ void __launch_bounds__(256, 2)
hgemm_k(const __nv_bfloat16* __restrict__ A, int lda, size_t Astr,
        const __nv_bfloat16* __restrict__ Wt, size_t Wstr,
        float* __restrict__ out, int ldc, size_t Cstr,
        int Kn, GemmAux gaux)
{
    constexpr int LDS  = 72;                 // 64 + 8 pad (bf16 elems)
    constexpr int AELE = MT * LDS;
    constexpr int BELE = NT * LDS;
    constexpr int STG  = AELE + BELE;
    constexpr int WMW  = MT / 32;            // warps along M
    constexpr int WNW  = 8 / WMW;            // warps along N
    constexpr int WN   = NT / WNW;           // warp n extent
    constexpr int NTL  = WN / 8;             // n8 tiles per warp
    constexpr int NJ   = NTL / 2;            // 16-col groups per warp
    constexpr int NST  = 4 * NJ;             // pipelined steps per chunk

    extern __shared__ __nv_bfloat16 sm[];

    const int zs = blockIdx.z;
    A   += zs * Astr;
    Wt  += zs * Wstr;
    out += zs * Cstr;
    const float* aux = gaux.a[zs];
    __nv_bfloat16* out_bf = gaux.bf[zs];

    const int tid  = threadIdx.x;
    const int lane = tid & 31;
    const int wid  = tid >> 5;
    const int wm   = wid % WMW;
    const int wn   = wid / WMW;

    const int row0 = blockIdx.y * MT;
    const int col0 = blockIdx.x * NT;

    const uint32_t sb = smem_u32(sm);

    auto issue = [&](int c, int s) {
        const int kt = c * 64;
        const uint32_t sA = sb + (uint32_t)s * STG * 2;
        const uint32_t sB = sA + AELE * 2;
        const __nv_bfloat16* Ap = A + (size_t)row0 * lda + kt;
#pragma unroll
        for (int i = 0; i < MT / 32; i++) {
            int idx = i * 256 + tid;
            int r = idx >> 3, c8 = (idx & 7) * 8;
            cpa16(sA + (r * LDS + c8) * 2, Ap + (size_t)r * lda + c8);
        }
        const __nv_bfloat16* Bp = Wt + (size_t)col0 * Kn + kt;
#pragma unroll
        for (int i = 0; i < NT / 32; i++) {
            int idx = i * 256 + tid;
            int r = idx >> 3, c8 = (idx & 7) * 8;
            cpa16(sB + (r * LDS + c8) * 2, Bp + (size_t)r * Kn + c8);
        }
        cpa_commit();
    };

    float acc[2][NTL][4];
#pragma unroll
    for (int mi = 0; mi < 2; mi++)
#pragma unroll
        for (int ni = 0; ni < NTL; ni++)
#pragma unroll
            for (int j = 0; j < 4; j++) acc[mi][ni][j] = 0.f;

    const int nch = Kn >> 6;
    issue(0, 0);
    if (nch > 1) issue(1, 1);

    const uint32_t aoff = ((wm * 32 + (lane & 15)) * LDS + (lane >> 4) * 8) * 2;
    const uint32_t boff = ((wn * WN + (lane & 7) + ((lane >> 4) & 1) * 8) * LDS
                           + ((lane >> 3) & 1) * 8) * 2;

    int s = 0;
    for (int c = 0; c < nch; c++) {
        if (c + 1 < nch) cpa_wait1(); else cpa_wait0();
        __syncthreads();
        if (c + 2 < nch) issue(c + 2, (s + 2) % 3);

        const uint32_t sA = sb + (uint32_t)s * STG * 2;
        const uint32_t sB = sA + AELE * 2;

        // ---- chunk prologue: fragments for step 0 ----
        uint32_t a_cur[2][4], a_nxt[2][4], b_cur[4], b_nxt[4];
        ldsm4(a_cur[0][0], a_cur[0][1], a_cur[0][2], a_cur[0][3], sA + aoff);
        ldsm4(a_cur[1][0], a_cur[1][1], a_cur[1][2], a_cur[1][3],
              sA + aoff + 16 * LDS * 2);
        ldsm4(b_cur[0], b_cur[1], b_cur[2], b_cur[3], sB + boff);

        // ---- flattened (ks, nj) steps with one-step lookahead ----
#pragma unroll
        for (int st = 0; st < NST; st++) {
            const int nj = st % NJ;
            if (st + 1 < NST) {
                const int ksn = (st + 1) / NJ, njn = (st + 1) % NJ;
                ldsm4(b_nxt[0], b_nxt[1], b_nxt[2], b_nxt[3],
                      sB + boff + njn * (16 * LDS * 2) + ksn * 32);
                if (njn == 0) {
                    ldsm4(a_nxt[0][0], a_nxt[0][1], a_nxt[0][2], a_nxt[0][3],
                          sA + aoff + ksn * 32);
                    ldsm4(a_nxt[1][0], a_nxt[1][1], a_nxt[1][2], a_nxt[1][3],
                          sA + aoff + 16 * LDS * 2 + ksn * 32);
                }
            }
            mma16816(acc[0][nj * 2 + 0], a_cur[0], b_cur[0], b_cur[1]);
            mma16816(acc[1][nj * 2 + 0], a_cur[1], b_cur[0], b_cur[1]);
            mma16816(acc[0][nj * 2 + 1], a_cur[0], b_cur[2], b_cur[3]);
            mma16816(acc[1][nj * 2 + 1], a_cur[1], b_cur[2], b_cur[3]);
            if (st + 1 < NST) {
#pragma unroll
                for (int j = 0; j < 4; j++) b_cur[j] = b_nxt[j];
                if ((st + 1) % NJ == 0) {
#pragma unroll
                    for (int mi = 0; mi < 2; mi++)
#pragma unroll
                        for (int j = 0; j < 4; j++) a_cur[mi][j] = a_nxt[mi][j];
                }
            }
        }
        s = (s + 1) % 3;
    }

    // ---- epilogue ----
#pragma unroll
    for (int mi = 0; mi < 2; mi++) {
        int r = row0 + wm * 32 + mi * 16 + (lane >> 2);
#pragma unroll
        for (int ni = 0; ni < NTL; ni++) {
            int cg = col0 + wn * WN + ni * 8 + (lane & 3) * 2;
#pragma unroll
            for (int half = 0; half < 2; half++) {
                int rr = r + half * 8;
                float v0 = acc[mi][ni][half * 2 + 0];
                float v1 = acc[mi][ni][half * 2 + 1];
                if (EPI == 2) {
                    v0 += aux[cg];     v0 = fmaxf(v0, 0.f) + log1pf(__expf(-fabsf(v0)));
                    v1 += aux[cg + 1]; v1 = fmaxf(v1, 0.f) + log1pf(__expf(-fabsf(v1)));
                } else if (EPI == 3) {
                    const float2 xv = *(const float2*)(aux + (size_t)rr * ldc + cg);
                    v0 += xv.x; v1 += xv.y;
                }
                if (EPI != 4) {
                    *(float2*)(out + (size_t)rr * ldc + cg) = make_float2(v0, v1);
                }
                if (EPI == 1) {
                    __nv_bfloat162 pk;
                    pk.x = __float2bfloat16(cg     < RK ? v0 : 0.f);
                    pk.y = __float2bfloat16(cg + 1 < RK ? v1 : 0.f);
                    *(__nv_bfloat162*)(out_bf + (size_t)rr * 64 + cg) = pk;
                } else if (EPI == 4) {
                    __nv_bfloat162 pk;
                    pk.x = __float2bfloat16(v0);
                    pk.y = __float2bfloat16(v1);
                    *(__nv_bfloat162*)(out_bf + (size_t)rr * ldc + cg) = pk;
                }
            }
        }
    }
}

// ---------------------------------------------------------------------------
// Depthwise causal conv (K=4) + bias + SiLU; 4 rows/thread; bf16 in/out
// ---------------------------------------------------------------------------
struct ConvArgs { const float* wc[2]; const float* bc[2]; };

__global__ void conv_silu_b(const __nv_bfloat16* __restrict__ uz, ConvArgs ca,
                            __nv_bfloat16* __restrict__ ub)
{
    int idx = blockIdx.x * blockDim.x + threadIdx.x;
    if (idx >= (Mrows / 4) * Cd) return;
    const int s = blockIdx.y;
    uz += (size_t)s * Mrows * TWOD;
    ub += (size_t)s * Mrows * Cd;
    const float* wc = ca.wc[s];
    const float* bc = ca.bc[s];

    int d  = idx % Cd;
    int rq = idx / Cd;
    int r0 = rq * 4;
    int l0 = r0 % Lh;

    float w0 = wc[d * 4 + 0], w1 = wc[d * 4 + 1];
    float w2 = wc[d * 4 + 2], w3 = wc[d * 4 + 3];
    float bv = bc[d];

    const __nv_bfloat16* base = uz + (size_t)r0 * TWOD + d;
    float xv[7];
#pragma unroll
    for (int j = 0; j < 7; j++) {
        int l = l0 + j - 3;
        xv[j] = (l >= 0) ? __bfloat162float(base[(ptrdiff_t)(j - 3) * TWOD]) : 0.f;
    }
#pragma unroll
    for (int j = 0; j < 4; j++) {
        float v = bv;
        v = fmaf(xv[j],     w0, v);
        v = fmaf(xv[j + 1], w1, v);
        v = fmaf(xv[j + 2], w2, v);
        v = fmaf(xv[j + 3], w3, v);
        float sv = v / (1.f + __expf(-v));
        ub[(size_t)(r0 + j) * Cd + d] = __float2bfloat16(sv);
    }
}

// ---------------------------------------------------------------------------
// Selective scan (stream-batched; blockIdx.y encodes s*Bb + b); u from bf16
// ---------------------------------------------------------------------------
struct ScanArgs { const float* Alog[2]; const float* Dsk[2]; };

__global__ void scan1_b(const float* __restrict__ dt,
                        const __nv_bfloat16* __restrict__ u,
                        const float* __restrict__ dbl, ScanArgs sa,
                        float* __restrict__ Pout, float* __restrict__ Hout)
{
    const int s = blockIdx.y >> 1;
    const int b = blockIdx.y & 1;
    dt   += (size_t)s * Mrows * Cd;
    u    += (size_t)s * Mrows * Cd;
    dbl  += (size_t)s * Mrows * DBLS;
    Pout += (size_t)s * Bb * Cd * NCh * NS;
    Hout += (size_t)s * Bb * Cd * NCh * NS;
    const float* Alog = sa.Alog[s];

    int d  = blockIdx.z * 256 + threadIdx.x;
    int ch = blockIdx.x;
    float An[NS];
#pragma unroll
    for (int n = 0; n < NS; n++) An[n] = -__expf(Alog[d * NS + n]);
    float h[NS] = {0.f, 0.f, 0.f, 0.f};
    float P[NS] = {1.f, 1.f, 1.f, 1.f};
    int l0 = ch * LCh;
    for (int l = l0; l < l0 + LCh; l++) {
        int r = b * Lh + l;
        float dtv = dt[(size_t)r * Cd + d];
        float uv  = __bfloat162float(u[(size_t)r * Cd + d]);
        float du  = dtv * uv;
        const float* Bp = dbl + (size_t)r * DBLS + RK;
#pragma unroll
        for (int n = 0; n < NS; n++) {
            float dA = __expf(dtv * An[n]);
            h[n] = fmaf(dA, h[n], du * Bp[n]);
            P[n] *= dA;
        }
    }
    size_t o = (((size_t)(b * Cd + d)) * NCh + ch) * NS;
#pragma unroll
    for (int n = 0; n < NS; n++) { Pout[o + n] = P[n]; Hout[o + n] = h[n]; }
}

__global__ void scan2_b(const float* __restrict__ P, float* __restrict__ Hc)
{
    int idx = blockIdx.x * 256 + threadIdx.x;
    if (idx >= 2 * Bb * Cd) return;
    float h[NS] = {0.f, 0.f, 0.f, 0.f};
    size_t base = (size_t)idx * NCh * NS;
    for (int ch = 0; ch < NCh; ch++) {
        size_t o = base + ch * NS;
#pragma unroll
        for (int n = 0; n < NS; n++) {
            float He = Hc[o + n];
            float Pv = P[o + n];
            Hc[o + n] = h[n];
            h[n] = fmaf(Pv, h[n], He);
        }
    }
}

__global__ void scan3_b(const float* __restrict__ dt,
                        const __nv_bfloat16* __restrict__ u,
                        const float* __restrict__ dbl,
                        const float* __restrict__ Hc, ScanArgs sa,
                        const __nv_bfloat16* __restrict__ uz,
                        __nv_bfloat16* __restrict__ yz)
{
    const int s = blockIdx.y >> 1;
    const int b = blockIdx.y & 1;
    dt += (size_t)s * Mrows * Cd;
    u  += (size_t)s * Mrows * Cd;
    uz += (size_t)s * Mrows * TWOD;
    yz += (size_t)s * Mrows * Cd;
    Hc += (size_t)s * Bb * Cd * NCh * NS;
    const float* dbl_self  = dbl + (size_t)s * Mrows * DBLS;
    const float* dbl_other = dbl + (size_t)(1 - s) * Mrows * DBLS;
    const float* Alog = sa.Alog[s];
    const float* Dskip = sa.Dsk[s];

    int d  = blockIdx.z * 256 + threadIdx.x;
    int ch = blockIdx.x;
    float An[NS];
#pragma unroll
    for (int n = 0; n < NS; n++) An[n] = -__expf(Alog[d * NS + n]);
    float h[NS];
    size_t ho = (((size_t)(b * Cd + d)) * NCh + ch) * NS;
#pragma unroll
    for (int n = 0; n < NS; n++) h[n] = Hc[ho + n];
    float dsk = Dskip[d];
    int l0 = ch * LCh;
    for (int l = l0; l < l0 + LCh; l++) {
        int r = b * Lh + l;
        float dtv = dt[(size_t)r * Cd + d];
        float uv  = __bfloat162float(u[(size_t)r * Cd + d]);
        float du  = dtv * uv;
        const float* Bp = dbl_self  + (size_t)r * DBLS + RK;
        const float* Cp = dbl_other + (size_t)r * DBLS + RK + NS;
        float y = uv * dsk;
#pragma unroll
        for (int n = 0; n < NS; n++) {
            float dA = __expf(dtv * An[n]);
            h[n] = fmaf(dA, h[n], du * Bp[n]);
            y = fmaf(h[n], Cp[n], y);
        }
        float z  = __bfloat162float(uz[(size_t)r * TWOD + Cd + d]);
        float sz = z / (1.f + __expf(-z));
        yz[(size_t)r * Cd + d] = __float2bfloat16(y * sz);
    }
}

// ---------------------------------------------------------------------------
// Launch (my idx 4 = in_proj stream 1 -> global ncu window idx 5)
// ---------------------------------------------------------------------------
extern "C" void kernel_launch(void* const* d_in, const int* in_sizes, int n_in,
                              void* d_out, int out_size)
{
    (void)in_sizes; (void)n_in; (void)out_size;

    float *xt, *mean, *rstd, *dbl, *dt, *P, *Hc;
    __nv_bfloat16 *xnb, *uzb, *ub, *dtrb, *yzb, *wint, *woutt, *wxpt, *wdtt;
    cudaGetSymbolAddress((void**)&xt,    g_xt);
    cudaGetSymbolAddress((void**)&xnb,   g_xnb);
    cudaGetSymbolAddress((void**)&mean,  g_mean);
    cudaGetSymbolAddress((void**)&rstd,  g_rstd);
    cudaGetSymbolAddress((void**)&uzb,   g_uzb);
    cudaGetSymbolAddress((void**)&ub,    g_ub);
    cudaGetSymbolAddress((void**)&dbl,   g_dbl);
    cudaGetSymbolAddress((void**)&dtrb,  g_dtrb);
    cudaGetSymbolAddress((void**)&dt,    g_dt);
    cudaGetSymbolAddress((void**)&yzb,   g_yzb);
    cudaGetSymbolAddress((void**)&P,     g_P);
    cudaGetSymbolAddress((void**)&Hc,    g_Hc);
    cudaGetSymbolAddress((void**)&wint,  g_wint);
    cudaGetSymbolAddress((void**)&woutt, g_woutt);
    cudaGetSymbolAddress((void**)&wxpt,  g_wxpt);
    cudaGetSymbolAddress((void**)&wdtt,  g_wdtt);

    const size_t SC  = (size_t)Mrows * Cd;
    const size_t SUZ = (size_t)Mrows * TWOD;

    const float* Xin[2] = { (const float*)d_in[0], (const float*)d_in[1] };
    const float *lng[2], *lnb[2], *Win[2], *Wcv[2], *bcv[2], *Wxp[2],
                *Wdt[2], *bdt[2], *Alog[2], *Dsk[2], *Wout[2];
    for (int s = 0; s < 2; s++) {
        int o = 2 + s * 11;
        lng[s]  = (const float*)d_in[o + 0];
        lnb[s]  = (const float*)d_in[o + 1];
        Win[s]  = (const float*)d_in[o + 2];
        Wcv[s]  = (const float*)d_in[o + 3];
        bcv[s]  = (const float*)d_in[o + 4];
        Wxp[s]  = (const float*)d_in[o + 5];
        Wdt[s]  = (const float*)d_in[o + 6];
        bdt[s]  = (const float*)d_in[o + 7];
        Alog[s] = (const float*)d_in[o + 8];
        Dsk[s]  = (const float*)d_in[o + 9];
        Wout[s] = (const float*)d_in[o + 10];
    }

    // 3-stage, BK=64 smem sizes
    const int SMB128 = 3 * (128 * 72 + 128 * 72) * 2;  // 110592
    const int SMB64  = 3 * (64 * 72 + 64 * 72) * 2;    // 55296
    cudaFuncSetAttribute(hgemm_k<128, 128, 4>, cudaFuncAttributeMaxDynamicSharedMemorySize, SMB128);
    cudaFuncSetAttribute(hgemm_k<128, 128, 2>, cudaFuncAttributeMaxDynamicSharedMemorySize, SMB128);
    cudaFuncSetAttribute(hgemm_k<128, 128, 3>, cudaFuncAttributeMaxDynamicSharedMemorySize, SMB128);
    cudaFuncSetAttribute(hgemm_k<64, 64, 1>,   cudaFuncAttributeMaxDynamicSharedMemorySize, SMB64);

    // ---- launch 0: weight prep ----
    WtArgs wa;
    for (int s = 0; s < 2; s++) {
        wa.W[s * 4 + 0] = Win[s];  wa.Wt[s * 4 + 0] = wint  + s * (size_t)TWOD * Cd;
        wa.W[s * 4 + 1] = Wout[s]; wa.Wt[s * 4 + 1] = woutt + s * (size_t)Cd * Cd;
        wa.W[s * 4 + 2] = Wxp[s];  wa.Wt[s * 4 + 2] = wxpt  + s * (size_t)64 * Cd;
        wa.W[s * 4 + 3] = Wdt[s];  wa.Wt[s * 4 + 3] = wdtt  + s * (size_t)Cd * 64;
    }
    wt_all_k<<<dim3(Cd / 32, TWOD / 32, 8), dim3(32, 8)>>>(wa);

    // ---- launch 1: LN stats (both streams) ----
    ln_stats_b<<<dim3((Mrows + 127) / 128, 2), 128>>>(Xin[0], Xin[1], mean, rstd);

    // ---- launch 2: transpose + norm (both streams) ----
    TnArgs ta;
    for (int s = 0; s < 2; s++) { ta.x[s] = Xin[s]; ta.g[s] = lng[s]; ta.lb[s] = lnb[s]; }
    tn_b<<<dim3(Lh / 32, Cd / 32, 2 * Bb), dim3(32, 8)>>>(ta, mean, rstd, xt, xnb);

    // ---- launches 3,4: in_proj per stream, bf16 output (idx 4 -> ncu) ----
    for (int s = 0; s < 2; s++) {
        GemmAux ipa = { { nullptr, nullptr }, { uzb + s * SUZ, nullptr } };
        hgemm_k<128, 128, 4><<<dim3(TWOD / 128, Mrows / 128, 1), 256, SMB128>>>(
            xnb + s * SC, Cd, 0, wint + s * (size_t)TWOD * Cd, 0,
            (float*)nullptr, TWOD, 0, Cd, ipa);
    }

    // ---- launch 5: conv + silu (both) ----
    ConvArgs ca = { { Wcv[0], Wcv[1] }, { bcv[0], bcv[1] } };
    conv_silu_b<<<dim3(((Mrows / 4) * Cd + 255) / 256, 2), 256>>>(uzb, ca, ub);

    // ---- launch 6: x_proj (both), 64x64 tiles for occupancy ----
    GemmAux xpa = { { nullptr, nullptr }, { dtrb, dtrb + (size_t)Mrows * 64 } };
    hgemm_k<64, 64, 1><<<dim3(1, Mrows / 64, 2), 256, SMB64>>>(
        ub, Cd, SC, wxpt, (size_t)64 * Cd,
        dbl, DBLS, (size_t)Mrows * DBLS, Cd, xpa);

    // ---- launch 7: dt proj + softplus (both) ----
    GemmAux dta = { { bdt[0], bdt[1] }, { nullptr, nullptr } };
    hgemm_k<128, 128, 2><<<dim3(Cd / 128, Mrows / 128, 2), 256, SMB128>>>(
        dtrb, 64, (size_t)Mrows * 64, wdtt, (size_t)Cd * 64,
        dt, Cd, SC, 64, dta);

    // ---- launches 8-10: selective scans (both) ----
    ScanArgs sa = { { Alog[0], Alog[1] }, { Dsk[0], Dsk[1] } };
    scan1_b<<<dim3(NCh, 2 * Bb, Cd / 256), 256>>>(dt, ub, dbl, sa, P, Hc);
    scan2_b<<<(2 * Bb * Cd + 255) / 256, 256>>>(P, Hc);
    scan3_b<<<dim3(NCh, 2 * Bb, Cd / 256), 256>>>(dt, ub, dbl, Hc, sa, uzb, yzb);

    // ---- launch 11: out_proj + residual (both) ----
    GemmAux opa = { { xt, xt + SC }, { nullptr, nullptr } };
    hgemm_k<128, 128, 3><<<dim3(Cd / 128, Mrows / 128, 2), 256, SMB128>>>(
        yzb, Cd, SC, woutt, (size_t)Cd * Cd,
        (float*)d_out, Cd, SC, Cd, opa);
}

// round 9
// speedup vs baseline: 1.0503x; 1.0503x over previous
#include <cuda_runtime.h>
#include <cuda_bf16.h>
#include <math.h>
#include <cstdint>

// ---------------------------------------------------------------------------
// Problem constants (fixed by setup_inputs)
// ---------------------------------------------------------------------------
#define Bb    2
#define Cd    768
#define Lh    4096            // H*W
#define Mrows (Bb*Lh)         // 8192
#define TWOD  1536
#define DBLS  64              // padded dt_raw|B|C row stride (56 -> 64)
#define RK    48
#define NS    4
#define NCh   64              // scan chunks per batch
#define LCh   64              // chunk length  (NCh*LCh == Lh)

// ---------------------------------------------------------------------------
// Static device scratch (no cudaMalloc allowed)
// ---------------------------------------------------------------------------
__device__ float          g_xt  [2][Mrows*Cd];     // residual (B,L,C) fp32
__device__ __nv_bfloat16  g_xnb [2][Mrows*Cd];     // layernormed x, bf16
__device__ float          g_mean[2][Mrows];
__device__ float          g_rstd[2][Mrows];
__device__ __nv_bfloat16  g_uzb [2][Mrows*TWOD];   // in_proj output bf16
__device__ __nv_bfloat16  g_ub  [2][Mrows*Cd];     // conv+silu bf16
__device__ float          g_dbl [2][Mrows*DBLS];   // dt_raw | B | C (stride 64)
__device__ __nv_bfloat16  g_dtrb[2][Mrows*64];     // dt_raw bf16, K padded to 64
__device__ __nv_bfloat16  g_dtb [2][Mrows*Cd];     // softplus dt, bf16
__device__ __nv_bfloat16  g_yzb [2][Mrows*Cd];     // y * silu(z) bf16
__device__ float          g_P   [2][Bb*Cd*NCh*NS];
__device__ float          g_Hc  [2][Bb*Cd*NCh*NS];
// transposed bf16 weights: Wt[n][k], zero padded
__device__ __nv_bfloat16  g_wint [2][TWOD*Cd];     // in_proj  [1536][768]
__device__ __nv_bfloat16  g_woutt[2][Cd*Cd];       // out_proj [768][768]
__device__ __nv_bfloat16  g_wxpt [2][64*Cd];       // x_proj   [64][768] (56 used)
__device__ __nv_bfloat16  g_wdtt [2][Cd*64];       // dt_proj  [768][64] (48 used)

// ---------------------------------------------------------------------------
// PTX helpers (sm_80-era: cp.async + ldmatrix + mma.sync -- works on sm_103)
// ---------------------------------------------------------------------------
__device__ __forceinline__ uint32_t smem_u32(const void* p) {
    uint32_t a;
    asm("{ .reg .u64 t; cvta.to.shared.u64 t, %1; cvt.u32.u64 %0, t; }"
        : "=r"(a) : "l"(p));
    return a;
}
__device__ __forceinline__ void cpa16(uint32_t s, const void* g) {
    asm volatile("cp.async.cg.shared.global [%0], [%1], 16;" :: "r"(s), "l"(g));
}
__device__ __forceinline__ void cpa_commit() {
    asm volatile("cp.async.commit_group;" ::: "memory");
}
__device__ __forceinline__ void cpa_wait1() {
    asm volatile("cp.async.wait_group 1;" ::: "memory");
}
__device__ __forceinline__ void cpa_wait0() {
    asm volatile("cp.async.wait_group 0;" ::: "memory");
}
__device__ __forceinline__ void ldsm4(uint32_t& r0, uint32_t& r1,
                                      uint32_t& r2, uint32_t& r3, uint32_t a) {
    asm volatile("ldmatrix.sync.aligned.m8n8.x4.shared.b16 {%0,%1,%2,%3}, [%4];"
                 : "=r"(r0), "=r"(r1), "=r"(r2), "=r"(r3) : "r"(a));
}
__device__ __forceinline__ void mma16816(float* d, const uint32_t* a,
                                         uint32_t b0, uint32_t b1) {
    asm volatile(
        "mma.sync.aligned.m16n8k16.row.col.f32.bf16.bf16.f32 "
        "{%0,%1,%2,%3}, {%4,%5,%6,%7}, {%8,%9}, {%0,%1,%2,%3};"
        : "+f"(d[0]), "+f"(d[1]), "+f"(d[2]), "+f"(d[3])
        : "r"(a[0]), "r"(a[1]), "r"(a[2]), "r"(a[3]), "r"(b0), "r"(b1));
}

// ---------------------------------------------------------------------------
// LayerNorm stats — 32 rows x 8 channel-groups per block, smem reduce.
// 512 blocks (vs 128 before): latency-bound -> BW-bound.
// ---------------------------------------------------------------------------
__global__ void ln_stats_b(const float* __restrict__ x0,
                           const float* __restrict__ x1,
                           float* __restrict__ mean, float* __restrict__ rstd)
{
    const int s  = blockIdx.y;
    const float* x = s ? x1 : x0;
    mean += s * Mrows; rstd += s * Mrows;

    const int lx = threadIdx.x & 31;     // row within 32-row group
    const int cg = threadIdx.x >> 5;     // channel group 0..7
    const int r  = blockIdx.x * 32 + lx;
    const int b  = r / Lh, l = r % Lh;   // 32 rows share b (Lh%32==0)
    const float* xp = x + (size_t)b * Cd * Lh + l;

    float sum = 0.f, sum2 = 0.f;
    const int c0 = cg * (Cd / 8);
#pragma unroll 8
    for (int c = c0; c < c0 + Cd / 8; c++) {
        float v = __ldg(xp + (size_t)c * Lh);
        sum += v;
        sum2 = fmaf(v, v, sum2);
    }
    __shared__ float ss[8][32], ss2[8][32];
    ss[cg][lx] = sum;
    ss2[cg][lx] = sum2;
    __syncthreads();
    if (cg == 0) {
#pragma unroll
        for (int i = 1; i < 8; i++) { sum += ss[i][lx]; sum2 += ss2[i][lx]; }
        float m   = sum * (1.f / Cd);
        float var = sum2 * (1.f / Cd) - m * m;
        mean[r] = m;
        rstd[r] = rsqrtf(var + 1e-5f);
    }
}

// ---------------------------------------------------------------------------
// Transpose BCHW -> (B,L,C), both streams (blockIdx.z = s*Bb + b)
// ---------------------------------------------------------------------------
struct TnArgs { const float* x[2]; const float* g[2]; const float* lb[2]; };

__global__ void tn_b(TnArgs a,
                     const float* __restrict__ mean, const float* __restrict__ rstd,
                     float* __restrict__ xt, __nv_bfloat16* __restrict__ xn)
{
    __shared__ float t[32][33];
    const int s = blockIdx.z >> 1;
    const int b = blockIdx.z & 1;
    const float* x = a.x[s];
    const float* g = a.g[s];
    const float* lb = a.lb[s];
    mean += s * Mrows; rstd += s * Mrows;
    xt += (size_t)s * Mrows * Cd;
    xn += (size_t)s * Mrows * Cd;

    int c0 = blockIdx.y * 32;
    int l0 = blockIdx.x * 32;
#pragma unroll
    for (int i = 0; i < 4; i++) {
        int c = c0 + threadIdx.y + i * 8;
        t[threadIdx.y + i * 8][threadIdx.x] =
            x[((size_t)b * Cd + c) * Lh + l0 + threadIdx.x];
    }
    __syncthreads();
#pragma unroll
    for (int i = 0; i < 4; i++) {
        int l = l0 + threadIdx.y + i * 8;
        int c = c0 + threadIdx.x;
        int r = b * Lh + l;
        float v = t[threadIdx.x][threadIdx.y + i * 8];
        size_t o = (size_t)r * Cd + c;
        xt[o] = v;
        xn[o] = __float2bfloat16((v - mean[r]) * rstd[r] * g[c] + lb[c]);
    }
}

// ---------------------------------------------------------------------------
// Batched weight transpose + fp32->bf16 + zero pad (8 matrices in one launch)
// ---------------------------------------------------------------------------
struct WtArgs { const float* W[8]; __nv_bfloat16* Wt[8]; };

__global__ void wt_all_k(WtArgs a)
{
    const int id = blockIdx.z;
    const int m  = id & 3;      // 0=in, 1=out, 2=xp, 3=dt
    const int Ks[4]  = {Cd, Cd, Cd, RK};
    const int Ns[4]  = {TWOD, Cd, 56, Cd};
    const int Kps[4] = {Cd, Cd, Cd, 64};
    const int Nps[4] = {TWOD, Cd, 64, Cd};
    const int bxs[4] = {Cd/32, Cd/32, Cd/32, 2};
    const int bys[4] = {TWOD/32, Cd/32, 2, Cd/32};
    if ((int)blockIdx.x >= bxs[m] || (int)blockIdx.y >= bys[m]) return;
    const int K = Ks[m], N = Ns[m], Kpad = Kps[m], Npad = Nps[m];
    const float* W = a.W[id];
    __nv_bfloat16* Wt = a.Wt[id];

    __shared__ float t[32][33];
    int k0 = blockIdx.x * 32, n0 = blockIdx.y * 32;
#pragma unroll
    for (int i = 0; i < 4; i++) {
        int k = k0 + threadIdx.y + i * 8;
        int n = n0 + threadIdx.x;
        t[threadIdx.y + i * 8][threadIdx.x] =
            (k < K && n < N) ? W[(size_t)k * N + n] : 0.f;
    }
    __syncthreads();
#pragma unroll
    for (int i = 0; i < 4; i++) {
        int n = n0 + threadIdx.y + i * 8;
        int k = k0 + threadIdx.x;
        if (n < Npad && k < Kpad)
            Wt[(size_t)n * Kpad + k] = __float2bfloat16(t[threadIdx.x][threadIdx.y + i * 8]);
    }
}

// ---------------------------------------------------------------------------
// HMMA bf16 GEMM: C[M,N] = A[M,K] @ Wt[N,K]^T, fp32 accumulate.
//   CTA tile MT x NT, BK=64, 256 threads = 8 warps, 3-stage cp.async pipeline,
//   flattened (ks,nj) steps with one-step register lookahead.
//   EPI 0: fp32 | 1: fp32 + bf16 dtrb copy (stride 64, zero c>=48)
//   EPI 2: softplus(v+aux[c]) -> bf16 only | 3: v+aux residual fp32 | 4: bf16 only
// ---------------------------------------------------------------------------
struct GemmAux { const float* a[2]; __nv_bfloat16* bf[2]; };

template<int MT, int NT, int EPI>
__global__ void __launch_bounds__(256, 2)
hgemm_k(const __nv_bfloat16* __restrict__ A, int lda, size_t Astr,
        const __nv_bfloat16* __restrict__ Wt, size_t Wstr,
        float* __restrict__ out, int ldc, size_t Cstr,
        int Kn, GemmAux gaux)
{
    constexpr int LDS  = 72;                 // 64 + 8 pad (bf16 elems)
    constexpr int AELE = MT * LDS;
    constexpr int BELE = NT * LDS;
    constexpr int STG  = AELE + BELE;
    constexpr int WMW  = MT / 32;            // warps along M
    constexpr int WNW  = 8 / WMW;            // warps along N
    constexpr int WN   = NT / WNW;           // warp n extent
    constexpr int NTL  = WN / 8;             // n8 tiles per warp
    constexpr int NJ   = NTL / 2;            // 16-col groups per warp
    constexpr int NST  = 4 * NJ;             // pipelined steps per chunk

    extern __shared__ __nv_bfloat16 sm[];

    const int zs = blockIdx.z;
    A   += zs * Astr;
    Wt  += zs * Wstr;
    if (EPI != 2 && EPI != 4) out += zs * Cstr;
    const float* aux = gaux.a[zs];
    __nv_bfloat16* out_bf = gaux.bf[zs];

    const int tid  = threadIdx.x;
    const int lane = tid & 31;
    const int wid  = tid >> 5;
    const int wm   = wid % WMW;
    const int wn   = wid / WMW;

    const int row0 = blockIdx.y * MT;
    const int col0 = blockIdx.x * NT;

    const uint32_t sb = smem_u32(sm);

    auto issue = [&](int c, int s) {
        const int kt = c * 64;
        const uint32_t sA = sb + (uint32_t)s * STG * 2;
        const uint32_t sB = sA + AELE * 2;
        const __nv_bfloat16* Ap = A + (size_t)row0 * lda + kt;
#pragma unroll
        for (int i = 0; i < MT / 32; i++) {
            int idx = i * 256 + tid;
            int r = idx >> 3, c8 = (idx & 7) * 8;
            cpa16(sA + (r * LDS + c8) * 2, Ap + (size_t)r * lda + c8);
        }
        const __nv_bfloat16* Bp = Wt + (size_t)col0 * Kn + kt;
#pragma unroll
        for (int i = 0; i < NT / 32; i++) {
            int idx = i * 256 + tid;
            int r = idx >> 3, c8 = (idx & 7) * 8;
            cpa16(sB + (r * LDS + c8) * 2, Bp + (size_t)r * Kn + c8);
        }
        cpa_commit();
    };

    float acc[2][NTL][4];
#pragma unroll
    for (int mi = 0; mi < 2; mi++)
#pragma unroll
        for (int ni = 0; ni < NTL; ni++)
#pragma unroll
            for (int j = 0; j < 4; j++) acc[mi][ni][j] = 0.f;

    const int nch = Kn >> 6;
    issue(0, 0);
    if (nch > 1) issue(1, 1);

    const uint32_t aoff = ((wm * 32 + (lane & 15)) * LDS + (lane >> 4) * 8) * 2;
    const uint32_t boff = ((wn * WN + (lane & 7) + ((lane >> 4) & 1) * 8) * LDS
                           + ((lane >> 3) & 1) * 8) * 2;

    int s = 0;
    for (int c = 0; c < nch; c++) {
        if (c + 1 < nch) cpa_wait1(); else cpa_wait0();
        __syncthreads();
        if (c + 2 < nch) issue(c + 2, (s + 2) % 3);

        const uint32_t sA = sb + (uint32_t)s * STG * 2;
        const uint32_t sB = sA + AELE * 2;

        uint32_t a_cur[2][4], a_nxt[2][4], b_cur[4], b_nxt[4];
        ldsm4(a_cur[0][0], a_cur[0][1], a_cur[0][2], a_cur[0][3], sA + aoff);
        ldsm4(a_cur[1][0], a_cur[1][1], a_cur[1][2], a_cur[1][3],
              sA + aoff + 16 * LDS * 2);
        ldsm4(b_cur[0], b_cur[1], b_cur[2], b_cur[3], sB + boff);

#pragma unroll
        for (int st = 0; st < NST; st++) {
            const int nj = st % NJ;
            if (st + 1 < NST) {
                const int ksn = (st + 1) / NJ, njn = (st + 1) % NJ;
                ldsm4(b_nxt[0], b_nxt[1], b_nxt[2], b_nxt[3],
                      sB + boff + njn * (16 * LDS * 2) + ksn * 32);
                if (njn == 0) {
                    ldsm4(a_nxt[0][0], a_nxt[0][1], a_nxt[0][2], a_nxt[0][3],
                          sA + aoff + ksn * 32);
                    ldsm4(a_nxt[1][0], a_nxt[1][1], a_nxt[1][2], a_nxt[1][3],
                          sA + aoff + 16 * LDS * 2 + ksn * 32);
                }
            }
            mma16816(acc[0][nj * 2 + 0], a_cur[0], b_cur[0], b_cur[1]);
            mma16816(acc[1][nj * 2 + 0], a_cur[1], b_cur[0], b_cur[1]);
            mma16816(acc[0][nj * 2 + 1], a_cur[0], b_cur[2], b_cur[3]);
            mma16816(acc[1][nj * 2 + 1], a_cur[1], b_cur[2], b_cur[3]);
            if (st + 1 < NST) {
#pragma unroll
                for (int j = 0; j < 4; j++) b_cur[j] = b_nxt[j];
                if ((st + 1) % NJ == 0) {
#pragma unroll
                    for (int mi = 0; mi < 2; mi++)
#pragma unroll
                        for (int j = 0; j < 4; j++) a_cur[mi][j] = a_nxt[mi][j];
                }
            }
        }
        s = (s + 1) % 3;
    }

    // ---- epilogue ----
#pragma unroll
    for (int mi = 0; mi < 2; mi++) {
        int r = row0 + wm * 32 + mi * 16 + (lane >> 2);
#pragma unroll
        for (int ni = 0; ni < NTL; ni++) {
            int cg = col0 + wn * WN + ni * 8 + (lane & 3) * 2;
#pragma unroll
            for (int half = 0; half < 2; half++) {
                int rr = r + half * 8;
                float v0 = acc[mi][ni][half * 2 + 0];
                float v1 = acc[mi][ni][half * 2 + 1];
                if (EPI == 2) {
                    v0 += aux[cg];     v0 = fmaxf(v0, 0.f) + log1pf(__expf(-fabsf(v0)));
                    v1 += aux[cg + 1]; v1 = fmaxf(v1, 0.f) + log1pf(__expf(-fabsf(v1)));
                    __nv_bfloat162 pk;
                    pk.x = __float2bfloat16(v0);
                    pk.y = __float2bfloat16(v1);
                    *(__nv_bfloat162*)(out_bf + (size_t)rr * ldc + cg) = pk;
                    continue;
                }
                if (EPI == 3) {
                    const float2 xv = *(const float2*)(aux + (size_t)rr * ldc + cg);
                    v0 += xv.x; v1 += xv.y;
                }
                if (EPI != 4) {
                    *(float2*)(out + (size_t)rr * ldc + cg) = make_float2(v0, v1);
                }
                if (EPI == 1) {
                    __nv_bfloat162 pk;
                    pk.x = __float2bfloat16(cg     < RK ? v0 : 0.f);
                    pk.y = __float2bfloat16(cg + 1 < RK ? v1 : 0.f);
                    *(__nv_bfloat162*)(out_bf + (size_t)rr * 64 + cg) = pk;
                } else if (EPI == 4) {
                    __nv_bfloat162 pk;
                    pk.x = __float2bfloat16(v0);
                    pk.y = __float2bfloat16(v1);
                    *(__nv_bfloat162*)(out_bf + (size_t)rr * ldc + cg) = pk;
                }
            }
        }
    }
}

// ---------------------------------------------------------------------------
// Depthwise causal conv (K=4) + bias + SiLU; 4 rows/thread; bf16 in/out
// ---------------------------------------------------------------------------
struct ConvArgs { const float* wc[2]; const float* bc[2]; };

__global__ void conv_silu_b(const __nv_bfloat16* __restrict__ uz, ConvArgs ca,
                            __nv_bfloat16* __restrict__ ub)
{
    int idx = blockIdx.x * blockDim.x + threadIdx.x;
    if (idx >= (Mrows / 4) * Cd) return;
    const int s = blockIdx.y;
    uz += (size_t)s * Mrows * TWOD;
    ub += (size_t)s * Mrows * Cd;
    const float* wc = ca.wc[s];
    const float* bc = ca.bc[s];

    int d  = idx % Cd;
    int rq = idx / Cd;
    int r0 = rq * 4;
    int l0 = r0 % Lh;

    float w0 = wc[d * 4 + 0], w1 = wc[d * 4 + 1];
    float w2 = wc[d * 4 + 2], w3 = wc[d * 4 + 3];
    float bv = bc[d];

    const __nv_bfloat16* base = uz + (size_t)r0 * TWOD + d;
    float xv[7];
#pragma unroll
    for (int j = 0; j < 7; j++) {
        int l = l0 + j - 3;
        xv[j] = (l >= 0) ? __bfloat162float(base[(ptrdiff_t)(j - 3) * TWOD]) : 0.f;
    }
#pragma unroll
    for (int j = 0; j < 4; j++) {
        float v = bv;
        v = fmaf(xv[j],     w0, v);
        v = fmaf(xv[j + 1], w1, v);
        v = fmaf(xv[j + 2], w2, v);
        v = fmaf(xv[j + 3], w3, v);
        float sv = v / (1.f + __expf(-v));
        ub[(size_t)(r0 + j) * Cd + d] = __float2bfloat16(sv);
    }
}

// ---------------------------------------------------------------------------
// Selective scan (stream-batched; blockIdx.y encodes s*Bb + b); dt/u bf16
// ---------------------------------------------------------------------------
struct ScanArgs { const float* Alog[2]; const float* Dsk[2]; };

__global__ void scan1_b(const __nv_bfloat16* __restrict__ dt,
                        const __nv_bfloat16* __restrict__ u,
                        const float* __restrict__ dbl, ScanArgs sa,
                        float* __restrict__ Pout, float* __restrict__ Hout)
{
    const int s = blockIdx.y >> 1;
    const int b = blockIdx.y & 1;
    dt   += (size_t)s * Mrows * Cd;
    u    += (size_t)s * Mrows * Cd;
    dbl  += (size_t)s * Mrows * DBLS;
    Pout += (size_t)s * Bb * Cd * NCh * NS;
    Hout += (size_t)s * Bb * Cd * NCh * NS;
    const float* Alog = sa.Alog[s];

    int d  = blockIdx.z * 256 + threadIdx.x;
    int ch = blockIdx.x;
    float An[NS];
#pragma unroll
    for (int n = 0; n < NS; n++) An[n] = -__expf(Alog[d * NS + n]);
    float h[NS] = {0.f, 0.f, 0.f, 0.f};
    float sdt = 0.f;
    int l0 = ch * LCh;
    for (int l = l0; l < l0 + LCh; l++) {
        int r = b * Lh + l;
        float dtv = __bfloat162float(dt[(size_t)r * Cd + d]);
        float uv  = __bfloat162float(u [(size_t)r * Cd + d]);
        float du  = dtv * uv;
        sdt += dtv;
        const float* Bp = dbl + (size_t)r * DBLS + RK;
#pragma unroll
        for (int n = 0; n < NS; n++) {
            float dA = __expf(dtv * An[n]);
            h[n] = fmaf(dA, h[n], du * Bp[n]);
        }
    }
    size_t o = (((size_t)(b * Cd + d)) * NCh + ch) * NS;
#pragma unroll
    for (int n = 0; n < NS; n++) {
        Pout[o + n] = __expf(sdt * An[n]);   // prod of dA = exp(An * sum dt)
        Hout[o + n] = h[n];
    }
}

__global__ void scan2_b(const float* __restrict__ P, float* __restrict__ Hc)
{
    int idx = blockIdx.x * 256 + threadIdx.x;
    if (idx >= 2 * Bb * Cd) return;
    float h[NS] = {0.f, 0.f, 0.f, 0.f};
    size_t base = (size_t)idx * NCh * NS;
    for (int ch = 0; ch < NCh; ch++) {
        size_t o = base + ch * NS;
#pragma unroll
        for (int n = 0; n < NS; n++) {
            float He = Hc[o + n];
            float Pv = P[o + n];
            Hc[o + n] = h[n];
            h[n] = fmaf(Pv, h[n], He);
        }
    }
}

__global__ void scan3_b(const __nv_bfloat16* __restrict__ dt,
                        const __nv_bfloat16* __restrict__ u,
                        const float* __restrict__ dbl,
                        const float* __restrict__ Hc, ScanArgs sa,
                        const __nv_bfloat16* __restrict__ uz,
                        __nv_bfloat16* __restrict__ yz)
{
    const int s = blockIdx.y >> 1;
    const int b = blockIdx.y & 1;
    dt += (size_t)s * Mrows * Cd;
    u  += (size_t)s * Mrows * Cd;
    uz += (size_t)s * Mrows * TWOD;
    yz += (size_t)s * Mrows * Cd;
    Hc += (size_t)s * Bb * Cd * NCh * NS;
    const float* dbl_self  = dbl + (size_t)s * Mrows * DBLS;
    const float* dbl_other = dbl + (size_t)(1 - s) * Mrows * DBLS;
    const float* Alog = sa.Alog[s];
    const float* Dskip = sa.Dsk[s];

    int d  = blockIdx.z * 256 + threadIdx.x;
    int ch = blockIdx.x;
    float An[NS];
#pragma unroll
    for (int n = 0; n < NS; n++) An[n] = -__expf(Alog[d * NS + n]);
    float h[NS];
    size_t ho = (((size_t)(b * Cd + d)) * NCh + ch) * NS;
#pragma unroll
    for (int n = 0; n < NS; n++) h[n] = Hc[ho + n];
    float dsk = Dskip[d];
    int l0 = ch * LCh;
    for (int l = l0; l < l0 + LCh; l++) {
        int r = b * Lh + l;
        float dtv = __bfloat162float(dt[(size_t)r * Cd + d]);
        float uv  = __bfloat162float(u [(size_t)r * Cd + d]);
        float du  = dtv * uv;
        const float* Bp = dbl_self  + (size_t)r * DBLS + RK;
        const float* Cp = dbl_other + (size_t)r * DBLS + RK + NS;
        float y = uv * dsk;
#pragma unroll
        for (int n = 0; n < NS; n++) {
            float dA = __expf(dtv * An[n]);
            h[n] = fmaf(dA, h[n], du * Bp[n]);
            y = fmaf(h[n], Cp[n], y);
        }
        float z  = __bfloat162float(uz[(size_t)r * TWOD + Cd + d]);
        float sz = z / (1.f + __expf(-z));
        yz[(size_t)r * Cd + d] = __float2bfloat16(y * sz);
    }
}

// ---------------------------------------------------------------------------
// Launch (my idx 4 = in_proj stream 1 -> global ncu window idx 5)
// ---------------------------------------------------------------------------
extern "C" void kernel_launch(void* const* d_in, const int* in_sizes, int n_in,
                              void* d_out, int out_size)
{
    (void)in_sizes; (void)n_in; (void)out_size;

    float *xt, *mean, *rstd, *dbl, *P, *Hc;
    __nv_bfloat16 *xnb, *uzb, *ub, *dtrb, *dtb, *yzb, *wint, *woutt, *wxpt, *wdtt;
    cudaGetSymbolAddress((void**)&xt,    g_xt);
    cudaGetSymbolAddress((void**)&xnb,   g_xnb);
    cudaGetSymbolAddress((void**)&mean,  g_mean);
    cudaGetSymbolAddress((void**)&rstd,  g_rstd);
    cudaGetSymbolAddress((void**)&uzb,   g_uzb);
    cudaGetSymbolAddress((void**)&ub,    g_ub);
    cudaGetSymbolAddress((void**)&dbl,   g_dbl);
    cudaGetSymbolAddress((void**)&dtrb,  g_dtrb);
    cudaGetSymbolAddress((void**)&dtb,   g_dtb);
    cudaGetSymbolAddress((void**)&yzb,   g_yzb);
    cudaGetSymbolAddress((void**)&P,     g_P);
    cudaGetSymbolAddress((void**)&Hc,    g_Hc);
    cudaGetSymbolAddress((void**)&wint,  g_wint);
    cudaGetSymbolAddress((void**)&woutt, g_woutt);
    cudaGetSymbolAddress((void**)&wxpt,  g_wxpt);
    cudaGetSymbolAddress((void**)&wdtt,  g_wdtt);

    const size_t SC  = (size_t)Mrows * Cd;
    const size_t SUZ = (size_t)Mrows * TWOD;

    const float* Xin[2] = { (const float*)d_in[0], (const float*)d_in[1] };
    const float *lng[2], *lnb[2], *Win[2], *Wcv[2], *bcv[2], *Wxp[2],
                *Wdt[2], *bdt[2], *Alog[2], *Dsk[2], *Wout[2];
    for (int s = 0; s < 2; s++) {
        int o = 2 + s * 11;
        lng[s]  = (const float*)d_in[o + 0];
        lnb[s]  = (const float*)d_in[o + 1];
        Win[s]  = (const float*)d_in[o + 2];
        Wcv[s]  = (const float*)d_in[o + 3];
        bcv[s]  = (const float*)d_in[o + 4];
        Wxp[s]  = (const float*)d_in[o + 5];
        Wdt[s]  = (const float*)d_in[o + 6];
        bdt[s]  = (const float*)d_in[o + 7];
        Alog[s] = (const float*)d_in[o + 8];
        Dsk[s]  = (const float*)d_in[o + 9];
        Wout[s] = (const float*)d_in[o + 10];
    }

    const int SMB128 = 3 * (128 * 72 + 128 * 72) * 2;  // 110592
    const int SMB64  = 3 * (64 * 72 + 64 * 72) * 2;    // 55296
    cudaFuncSetAttribute(hgemm_k<128, 128, 4>, cudaFuncAttributeMaxDynamicSharedMemorySize, SMB128);
    cudaFuncSetAttribute(hgemm_k<128, 128, 2>, cudaFuncAttributeMaxDynamicSharedMemorySize, SMB128);
    cudaFuncSetAttribute(hgemm_k<128, 128, 3>, cudaFuncAttributeMaxDynamicSharedMemorySize, SMB128);
    cudaFuncSetAttribute(hgemm_k<64, 64, 1>,   cudaFuncAttributeMaxDynamicSharedMemorySize, SMB64);

    // ---- launch 0: weight prep ----
    WtArgs wa;
    for (int s = 0; s < 2; s++) {
        wa.W[s * 4 + 0] = Win[s];  wa.Wt[s * 4 + 0] = wint  + s * (size_t)TWOD * Cd;
        wa.W[s * 4 + 1] = Wout[s]; wa.Wt[s * 4 + 1] = woutt + s * (size_t)Cd * Cd;
        wa.W[s * 4 + 2] = Wxp[s];  wa.Wt[s * 4 + 2] = wxpt  + s * (size_t)64 * Cd;
        wa.W[s * 4 + 3] = Wdt[s];  wa.Wt[s * 4 + 3] = wdtt  + s * (size_t)Cd * 64;
    }
    wt_all_k<<<dim3(Cd / 32, TWOD / 32, 8), dim3(32, 8)>>>(wa);

    // ---- launch 1: LN stats (both streams, 8-way parallel reduce) ----
    ln_stats_b<<<dim3(Mrows / 32, 2), 256>>>(Xin[0], Xin[1], mean, rstd);

    // ---- launch 2: transpose + norm (both streams) ----
    TnArgs ta;
    for (int s = 0; s < 2; s++) { ta.x[s] = Xin[s]; ta.g[s] = lng[s]; ta.lb[s] = lnb[s]; }
    tn_b<<<dim3(Lh / 32, Cd / 32, 2 * Bb), dim3(32, 8)>>>(ta, mean, rstd, xt, xnb);

    // ---- launches 3,4: in_proj per stream, bf16 output (idx 4 -> ncu) ----
    for (int s = 0; s < 2; s++) {
        GemmAux ipa = { { nullptr, nullptr }, { uzb + s * SUZ, nullptr } };
        hgemm_k<128, 128, 4><<<dim3(TWOD / 128, Mrows / 128, 1), 256, SMB128>>>(
            xnb + s * SC, Cd, 0, wint + s * (size_t)TWOD * Cd, 0,
            (float*)nullptr, TWOD, 0, Cd, ipa);
    }

    // ---- launch 5: conv + silu (both) ----
    ConvArgs ca = { { Wcv[0], Wcv[1] }, { bcv[0], bcv[1] } };
    conv_silu_b<<<dim3(((Mrows / 4) * Cd + 255) / 256, 2), 256>>>(uzb, ca, ub);

    // ---- launch 6: x_proj (both), 64x64 tiles ----
    GemmAux xpa = { { nullptr, nullptr }, { dtrb, dtrb + (size_t)Mrows * 64 } };
    hgemm_k<64, 64, 1><<<dim3(1, Mrows / 64, 2), 256, SMB64>>>(
        ub, Cd, SC, wxpt, (size_t)64 * Cd,
        dbl, DBLS, (size_t)Mrows * DBLS, Cd, xpa);

    // ---- launch 7: dt proj + softplus -> bf16 (both) ----
    GemmAux dta = { { bdt[0], bdt[1] }, { dtb, dtb + SC } };
    hgemm_k<128, 128, 2><<<dim3(Cd / 128, Mrows / 128, 2), 256, SMB128>>>(
        dtrb, 64, (size_t)Mrows * 64, wdtt, (size_t)Cd * 64,
        (float*)nullptr, Cd, 0, 64, dta);

    // ---- launches 8-10: selective scans (both) ----
    ScanArgs sa = { { Alog[0], Alog[1] }, { Dsk[0], Dsk[1] } };
    scan1_b<<<dim3(NCh, 2 * Bb, Cd / 256), 256>>>(dtb, ub, dbl, sa, P, Hc);
    scan2_b<<<(2 * Bb * Cd + 255) / 256, 256>>>(P, Hc);
    scan3_b<<<dim3(NCh, 2 * Bb, Cd / 256), 256>>>(dtb, ub, dbl, Hc, sa, uzb, yzb);

    // ---- launch 11: out_proj + residual (both) ----
    GemmAux opa = { { xt, xt + SC }, { nullptr, nullptr } };
    hgemm_k<128, 128, 3><<<dim3(Cd / 128, Mrows / 128, 2), 256, SMB128>>>(
        yzb, Cd, SC, woutt, (size_t)Cd * Cd,
        (float*)d_out, Cd, SC, Cd, opa);
}

// round 11
// speedup vs baseline: 1.1003x; 1.0476x over previous
#include <cuda_runtime.h>
#include <cuda_bf16.h>
#include <math.h>
#include <cstdint>

// ---------------------------------------------------------------------------
// Problem constants (fixed by setup_inputs)
// ---------------------------------------------------------------------------
#define Bb    2
#define Cd    768
#define Lh    4096            // H*W
#define Mrows (Bb*Lh)         // 8192
#define TWOD  1536
#define DBLS  64              // padded dt_raw|B|C row stride (56 -> 64)
#define RK    48
#define NS    4
#define NCh   64              // scan chunks per batch
#define LCh   64              // chunk length  (NCh*LCh == Lh)

// ---------------------------------------------------------------------------
// Static device scratch (no cudaMalloc allowed)
// ---------------------------------------------------------------------------
__device__ float          g_xt  [2][Mrows*Cd];     // residual (B,L,C) fp32
__device__ __nv_bfloat16  g_xnb [2][Mrows*Cd];     // layernormed x, bf16
__device__ float          g_mean[2][Mrows];
__device__ float          g_rstd[2][Mrows];
__device__ __nv_bfloat16  g_uzb [2][Mrows*TWOD];   // in_proj output bf16
__device__ __nv_bfloat16  g_ub  [2][Mrows*Cd];     // conv+silu bf16
__device__ float          g_dbl [2][Mrows*DBLS];   // dt_raw | B | C (stride 64)
__device__ __nv_bfloat16  g_dtrb[2][Mrows*64];     // dt_raw bf16, K padded to 64
__device__ __nv_bfloat16  g_dtb [2][Mrows*Cd];     // softplus dt, bf16
__device__ __nv_bfloat16  g_yzb [2][Mrows*Cd];     // y * silu(z) bf16
__device__ float          g_P   [2][Bb*Cd*NCh*NS];
__device__ float          g_Hc  [2][Bb*Cd*NCh*NS];
// transposed bf16 weights: Wt[n][k], zero padded
__device__ __nv_bfloat16  g_wint [2][TWOD*Cd];     // in_proj  [1536][768]
__device__ __nv_bfloat16  g_woutt[2][Cd*Cd];       // out_proj [768][768]
__device__ __nv_bfloat16  g_wxpt [2][64*Cd];       // x_proj   [64][768] (56 used)
__device__ __nv_bfloat16  g_wdtt [2][Cd*64];       // dt_proj  [768][64] (48 used)

// ---------------------------------------------------------------------------
// PTX helpers (sm_80-era: cp.async + ldmatrix + mma.sync -- works on sm_103)
// ---------------------------------------------------------------------------
__device__ __forceinline__ uint32_t smem_u32(const void* p) {
    uint32_t a;
    asm("{ .reg .u64 t; cvta.to.shared.u64 t, %1; cvt.u32.u64 %0, t; }"
        : "=r"(a) : "l"(p));
    return a;
}
__device__ __forceinline__ void cpa16(uint32_t s, const void* g) {
    asm volatile("cp.async.cg.shared.global [%0], [%1], 16;" :: "r"(s), "l"(g));
}
__device__ __forceinline__ void cpa_commit() {
    asm volatile("cp.async.commit_group;" ::: "memory");
}
__device__ __forceinline__ void cpa_wait1() {
    asm volatile("cp.async.wait_group 1;" ::: "memory");
}
__device__ __forceinline__ void cpa_wait0() {
    asm volatile("cp.async.wait_group 0;" ::: "memory");
}
__device__ __forceinline__ void ldsm4(uint32_t& r0, uint32_t& r1,
                                      uint32_t& r2, uint32_t& r3, uint32_t a) {
    asm volatile("ldmatrix.sync.aligned.m8n8.x4.shared.b16 {%0,%1,%2,%3}, [%4];"
                 : "=r"(r0), "=r"(r1), "=r"(r2), "=r"(r3) : "r"(a));
}
__device__ __forceinline__ void mma16816(float* d, const uint32_t* a,
                                         uint32_t b0, uint32_t b1) {
    asm volatile(
        "mma.sync.aligned.m16n8k16.row.col.f32.bf16.bf16.f32 "
        "{%0,%1,%2,%3}, {%4,%5,%6,%7}, {%8,%9}, {%0,%1,%2,%3};"
        : "+f"(d[0]), "+f"(d[1]), "+f"(d[2]), "+f"(d[3])
        : "r"(a[0]), "r"(a[1]), "r"(a[2]), "r"(a[3]), "r"(b0), "r"(b1));
}

// ---------------------------------------------------------------------------
// LayerNorm stats — 32 rows x 8 channel-groups per block, smem reduce.
// ---------------------------------------------------------------------------
__global__ void ln_stats_b(const float* __restrict__ x0,
                           const float* __restrict__ x1,
                           float* __restrict__ mean, float* __restrict__ rstd)
{
    const int s  = blockIdx.y;
    const float* x = s ? x1 : x0;
    mean += s * Mrows; rstd += s * Mrows;

    const int lx = threadIdx.x & 31;
    const int cg = threadIdx.x >> 5;
    const int r  = blockIdx.x * 32 + lx;
    const int b  = r / Lh, l = r % Lh;
    const float* xp = x + (size_t)b * Cd * Lh + l;

    float sum = 0.f, sum2 = 0.f;
    const int c0 = cg * (Cd / 8);
#pragma unroll 8
    for (int c = c0; c < c0 + Cd / 8; c++) {
        float v = __ldg(xp + (size_t)c * Lh);
        sum += v;
        sum2 = fmaf(v, v, sum2);
    }
    __shared__ float ss[8][32], ss2[8][32];
    ss[cg][lx] = sum;
    ss2[cg][lx] = sum2;
    __syncthreads();
    if (cg == 0) {
#pragma unroll
        for (int i = 1; i < 8; i++) { sum += ss[i][lx]; sum2 += ss2[i][lx]; }
        float m   = sum * (1.f / Cd);
        float var = sum2 * (1.f / Cd) - m * m;
        mean[r] = m;
        rstd[r] = rsqrtf(var + 1e-5f);
    }
}

// ---------------------------------------------------------------------------
// Transpose BCHW -> (B,L,C), both streams (blockIdx.z = s*Bb + b)
// ---------------------------------------------------------------------------
struct TnArgs { const float* x[2]; const float* g[2]; const float* lb[2]; };

__global__ void tn_b(TnArgs a,
                     const float* __restrict__ mean, const float* __restrict__ rstd,
                     float* __restrict__ xt, __nv_bfloat16* __restrict__ xn)
{
    __shared__ float t[32][33];
    const int s = blockIdx.z >> 1;
    const int b = blockIdx.z & 1;
    const float* x = a.x[s];
    const float* g = a.g[s];
    const float* lb = a.lb[s];
    mean += s * Mrows; rstd += s * Mrows;
    xt += (size_t)s * Mrows * Cd;
    xn += (size_t)s * Mrows * Cd;

    int c0 = blockIdx.y * 32;
    int l0 = blockIdx.x * 32;
#pragma unroll
    for (int i = 0; i < 4; i++) {
        int c = c0 + threadIdx.y + i * 8;
        t[threadIdx.y + i * 8][threadIdx.x] =
            x[((size_t)b * Cd + c) * Lh + l0 + threadIdx.x];
    }
    __syncthreads();
#pragma unroll
    for (int i = 0; i < 4; i++) {
        int l = l0 + threadIdx.y + i * 8;
        int c = c0 + threadIdx.x;
        int r = b * Lh + l;
        float v = t[threadIdx.x][threadIdx.y + i * 8];
        size_t o = (size_t)r * Cd + c;
        xt[o] = v;
        xn[o] = __float2bfloat16((v - mean[r]) * rstd[r] * g[c] + lb[c]);
    }
}

// ---------------------------------------------------------------------------
// Batched weight transpose + fp32->bf16 + zero pad (8 matrices in one launch)
// ---------------------------------------------------------------------------
struct WtArgs { const float* W[8]; __nv_bfloat16* Wt[8]; };

__global__ void wt_all_k(WtArgs a)
{
    const int id = blockIdx.z;
    const int m  = id & 3;      // 0=in, 1=out, 2=xp, 3=dt
    const int Ks[4]  = {Cd, Cd, Cd, RK};
    const int Ns[4]  = {TWOD, Cd, 56, Cd};
    const int Kps[4] = {Cd, Cd, Cd, 64};
    const int Nps[4] = {TWOD, Cd, 64, Cd};
    const int bxs[4] = {Cd/32, Cd/32, Cd/32, 2};
    const int bys[4] = {TWOD/32, Cd/32, 2, Cd/32};
    if ((int)blockIdx.x >= bxs[m] || (int)blockIdx.y >= bys[m]) return;
    const int K = Ks[m], N = Ns[m], Kpad = Kps[m], Npad = Nps[m];
    const float* W = a.W[id];
    __nv_bfloat16* Wt = a.Wt[id];

    __shared__ float t[32][33];
    int k0 = blockIdx.x * 32, n0 = blockIdx.y * 32;
#pragma unroll
    for (int i = 0; i < 4; i++) {
        int k = k0 + threadIdx.y + i * 8;
        int n = n0 + threadIdx.x;
        t[threadIdx.y + i * 8][threadIdx.x] =
            (k < K && n < N) ? W[(size_t)k * N + n] : 0.f;
    }
    __syncthreads();
#pragma unroll
    for (int i = 0; i < 4; i++) {
        int n = n0 + threadIdx.y + i * 8;
        int k = k0 + threadIdx.x;
        if (n < Npad && k < Kpad)
            Wt[(size_t)n * Kpad + k] = __float2bfloat16(t[threadIdx.x][threadIdx.y + i * 8]);
    }
}

// ---------------------------------------------------------------------------
// HMMA bf16 GEMM — occupancy shape: 64x64 CTA tile, 128 threads (4 warps,
// 2x2 warp grid, 32x32 warp tiles), BK=64, 2-buffer / 2-deep cp.async:
//   pre-issue groups 0,1; per chunk: wait_group 1 (group c DONE), consume
//   buffer c&1, sync, re-issue group c+2 into that buffer.
// regs ~72, smem 36KB -> 6 CTAs/SM = 24 warps/SM.
//   EPI 0: fp32 | 1: fp32 + bf16 dtrb copy (stride 64, zero c>=48)
//   EPI 2: softplus(v+aux[c]) -> bf16 | 3: v+aux residual fp32 | 4: bf16 only
// ---------------------------------------------------------------------------
struct GemmAux { const float* a[2]; __nv_bfloat16* bf[2]; };

template<int EPI>
__global__ void __launch_bounds__(128, 6)
hgemm_k(const __nv_bfloat16* __restrict__ A, int lda, size_t Astr,
        const __nv_bfloat16* __restrict__ Wt, size_t Wstr,
        float* __restrict__ out, int ldc, size_t Cstr,
        int Kn, GemmAux gaux)
{
    constexpr int MT   = 64;
    constexpr int NT   = 64;
    constexpr int LDS  = 72;                 // 64 + 8 pad (bf16 elems)
    constexpr int AELE = MT * LDS;
    constexpr int BELE = NT * LDS;
    constexpr int STG  = AELE + BELE;
    constexpr int NTL  = 4;                  // n8-tiles per warp
    constexpr int NJ   = 2;                  // 16-col groups per warp
    constexpr int NST  = 4 * NJ;             // (ks,nj) steps per chunk

    __shared__ __nv_bfloat16 sm[2 * STG];

    const int zs = blockIdx.z;
    A   += zs * Astr;
    Wt  += zs * Wstr;
    if (EPI != 2 && EPI != 4) out += zs * Cstr;
    const float* aux = gaux.a[zs];
    __nv_bfloat16* out_bf = gaux.bf[zs];

    const int tid  = threadIdx.x;
    const int lane = tid & 31;
    const int wid  = tid >> 5;
    const int wm   = wid & 1;
    const int wn   = wid >> 1;

    const int row0 = blockIdx.y * MT;
    const int col0 = blockIdx.x * NT;

    const uint32_t sb = smem_u32(sm);

    auto issue = [&](int c, int s) {
        const int kt = c * 64;
        const uint32_t sA = sb + (uint32_t)s * STG * 2;
        const uint32_t sB = sA + AELE * 2;
        const __nv_bfloat16* Ap = A + (size_t)row0 * lda + kt;
#pragma unroll
        for (int i = 0; i < 4; i++) {
            int idx = i * 128 + tid;
            int r = idx >> 3, c8 = (idx & 7) * 8;
            cpa16(sA + (r * LDS + c8) * 2, Ap + (size_t)r * lda + c8);
        }
        const __nv_bfloat16* Bp = Wt + (size_t)col0 * Kn + kt;
#pragma unroll
        for (int i = 0; i < 4; i++) {
            int idx = i * 128 + tid;
            int r = idx >> 3, c8 = (idx & 7) * 8;
            cpa16(sB + (r * LDS + c8) * 2, Bp + (size_t)r * Kn + c8);
        }
        cpa_commit();
    };

    float acc[2][NTL][4];
#pragma unroll
    for (int mi = 0; mi < 2; mi++)
#pragma unroll
        for (int ni = 0; ni < NTL; ni++)
#pragma unroll
            for (int j = 0; j < 4; j++) acc[mi][ni][j] = 0.f;

    const int nch = Kn >> 6;
    issue(0, 0);
    if (nch > 1) issue(1, 1);

    const uint32_t aoff = ((wm * 32 + (lane & 15)) * LDS + (lane >> 4) * 8) * 2;
    const uint32_t boff = ((wn * 32 + (lane & 7) + ((lane >> 4) & 1) * 8) * LDS
                           + ((lane >> 3) & 1) * 8) * 2;

    for (int c = 0; c < nch; c++) {
        const int s = c & 1;
        if (c + 1 < nch) cpa_wait1(); else cpa_wait0();  // group c complete
        __syncthreads();

        const uint32_t sA = sb + (uint32_t)s * STG * 2;
        const uint32_t sB = sA + AELE * 2;

        uint32_t a_cur[2][4], a_nxt[2][4], b_cur[4], b_nxt[4];
        ldsm4(a_cur[0][0], a_cur[0][1], a_cur[0][2], a_cur[0][3], sA + aoff);
        ldsm4(a_cur[1][0], a_cur[1][1], a_cur[1][2], a_cur[1][3],
              sA + aoff + 16 * LDS * 2);
        ldsm4(b_cur[0], b_cur[1], b_cur[2], b_cur[3], sB + boff);

#pragma unroll
        for (int st = 0; st < NST; st++) {
            const int nj = st % NJ;
            if (st + 1 < NST) {
                const int ksn = (st + 1) / NJ, njn = (st + 1) % NJ;
                ldsm4(b_nxt[0], b_nxt[1], b_nxt[2], b_nxt[3],
                      sB + boff + njn * (16 * LDS * 2) + ksn * 32);
                if (njn == 0) {
                    ldsm4(a_nxt[0][0], a_nxt[0][1], a_nxt[0][2], a_nxt[0][3],
                          sA + aoff + ksn * 32);
                    ldsm4(a_nxt[1][0], a_nxt[1][1], a_nxt[1][2], a_nxt[1][3],
                          sA + aoff + 16 * LDS * 2 + ksn * 32);
                }
            }
            mma16816(acc[0][nj * 2 + 0], a_cur[0], b_cur[0], b_cur[1]);
            mma16816(acc[1][nj * 2 + 0], a_cur[1], b_cur[0], b_cur[1]);
            mma16816(acc[0][nj * 2 + 1], a_cur[0], b_cur[2], b_cur[3]);
            mma16816(acc[1][nj * 2 + 1], a_cur[1], b_cur[2], b_cur[3]);
            if (st + 1 < NST) {
#pragma unroll
                for (int j = 0; j < 4; j++) b_cur[j] = b_nxt[j];
                if ((st + 1) % NJ == 0) {
#pragma unroll
                    for (int mi = 0; mi < 2; mi++)
#pragma unroll
                        for (int j = 0; j < 4; j++) a_cur[mi][j] = a_nxt[mi][j];
                }
            }
        }
        __syncthreads();                       // buffer s fully consumed
        if (c + 2 < nch) issue(c + 2, s);      // refill freed buffer
    }

    // ---- epilogue ----
#pragma unroll
    for (int mi = 0; mi < 2; mi++) {
        int r = row0 + wm * 32 + mi * 16 + (lane >> 2);
#pragma unroll
        for (int ni = 0; ni < NTL; ni++) {
            int cg = col0 + wn * 32 + ni * 8 + (lane & 3) * 2;
#pragma unroll
            for (int half = 0; half < 2; half++) {
                int rr = r + half * 8;
                float v0 = acc[mi][ni][half * 2 + 0];
                float v1 = acc[mi][ni][half * 2 + 1];
                if (EPI == 2) {
                    v0 += aux[cg];     v0 = fmaxf(v0, 0.f) + log1pf(__expf(-fabsf(v0)));
                    v1 += aux[cg + 1]; v1 = fmaxf(v1, 0.f) + log1pf(__expf(-fabsf(v1)));
                    __nv_bfloat162 pk;
                    pk.x = __float2bfloat16(v0);
                    pk.y = __float2bfloat16(v1);
                    *(__nv_bfloat162*)(out_bf + (size_t)rr * ldc + cg) = pk;
                    continue;
                }
                if (EPI == 3) {
                    const float2 xv = *(const float2*)(aux + (size_t)rr * ldc + cg);
                    v0 += xv.x; v1 += xv.y;
                }
                if (EPI != 4) {
                    *(float2*)(out + (size_t)rr * ldc + cg) = make_float2(v0, v1);
                }
                if (EPI == 1) {
                    __nv_bfloat162 pk;
                    pk.x = __float2bfloat16(cg     < RK ? v0 : 0.f);
                    pk.y = __float2bfloat16(cg + 1 < RK ? v1 : 0.f);
                    *(__nv_bfloat162*)(out_bf + (size_t)rr * 64 + cg) = pk;
                } else if (EPI == 4) {
                    __nv_bfloat162 pk;
                    pk.x = __float2bfloat16(v0);
                    pk.y = __float2bfloat16(v1);
                    *(__nv_bfloat162*)(out_bf + (size_t)rr * ldc + cg) = pk;
                }
            }
        }
    }
}

// ---------------------------------------------------------------------------
// Depthwise causal conv (K=4) + bias + SiLU; 4 rows/thread; bf16 in/out
// ---------------------------------------------------------------------------
struct ConvArgs { const float* wc[2]; const float* bc[2]; };

__global__ void conv_silu_b(const __nv_bfloat16* __restrict__ uz, ConvArgs ca,
                            __nv_bfloat16* __restrict__ ub)
{
    int idx = blockIdx.x * blockDim.x + threadIdx.x;
    if (idx >= (Mrows / 4) * Cd) return;
    const int s = blockIdx.y;
    uz += (size_t)s * Mrows * TWOD;
    ub += (size_t)s * Mrows * Cd;
    const float* wc = ca.wc[s];
    const float* bc = ca.bc[s];

    int d  = idx % Cd;
    int rq = idx / Cd;
    int r0 = rq * 4;
    int l0 = r0 % Lh;

    float w0 = wc[d * 4 + 0], w1 = wc[d * 4 + 1];
    float w2 = wc[d * 4 + 2], w3 = wc[d * 4 + 3];
    float bv = bc[d];

    const __nv_bfloat16* base = uz + (size_t)r0 * TWOD + d;
    float xv[7];
#pragma unroll
    for (int j = 0; j < 7; j++) {
        int l = l0 + j - 3;
        xv[j] = (l >= 0) ? __bfloat162float(base[(ptrdiff_t)(j - 3) * TWOD]) : 0.f;
    }
#pragma unroll
    for (int j = 0; j < 4; j++) {
        float v = bv;
        v = fmaf(xv[j],     w0, v);
        v = fmaf(xv[j + 1], w1, v);
        v = fmaf(xv[j + 2], w2, v);
        v = fmaf(xv[j + 3], w3, v);
        float sv = v / (1.f + __expf(-v));
        ub[(size_t)(r0 + j) * Cd + d] = __float2bfloat16(sv);
    }
}

// ---------------------------------------------------------------------------
// Selective scan (stream-batched; blockIdx.y encodes s*Bb + b); dt/u bf16
// ---------------------------------------------------------------------------
struct ScanArgs { const float* Alog[2]; const float* Dsk[2]; };

__global__ void scan1_b(const __nv_bfloat16* __restrict__ dt,
                        const __nv_bfloat16* __restrict__ u,
                        const float* __restrict__ dbl, ScanArgs sa,
                        float* __restrict__ Pout, float* __restrict__ Hout)
{
    const int s = blockIdx.y >> 1;
    const int b = blockIdx.y & 1;
    dt   += (size_t)s * Mrows * Cd;
    u    += (size_t)s * Mrows * Cd;
    dbl  += (size_t)s * Mrows * DBLS;
    Pout += (size_t)s * Bb * Cd * NCh * NS;
    Hout += (size_t)s * Bb * Cd * NCh * NS;
    const float* Alog = sa.Alog[s];

    int d  = blockIdx.z * 256 + threadIdx.x;
    int ch = blockIdx.x;
    float An[NS];
#pragma unroll
    for (int n = 0; n < NS; n++) An[n] = -__expf(Alog[d * NS + n]);
    float h[NS] = {0.f, 0.f, 0.f, 0.f};
    float sdt = 0.f;
    int l0 = ch * LCh;
    for (int l = l0; l < l0 + LCh; l++) {
        int r = b * Lh + l;
        float dtv = __bfloat162float(dt[(size_t)r * Cd + d]);
        float uv  = __bfloat162float(u [(size_t)r * Cd + d]);
        float du  = dtv * uv;
        sdt += dtv;
        const float* Bp = dbl + (size_t)r * DBLS + RK;
#pragma unroll
        for (int n = 0; n < NS; n++) {
            float dA = __expf(dtv * An[n]);
            h[n] = fmaf(dA, h[n], du * Bp[n]);
        }
    }
    size_t o = (((size_t)(b * Cd + d)) * NCh + ch) * NS;
#pragma unroll
    for (int n = 0; n < NS; n++) {
        Pout[o + n] = __expf(sdt * An[n]);
        Hout[o + n] = h[n];
    }
}

__global__ void scan2_b(const float* __restrict__ P, float* __restrict__ Hc)
{
    int idx = blockIdx.x * 256 + threadIdx.x;
    if (idx >= 2 * Bb * Cd) return;
    float h[NS] = {0.f, 0.f, 0.f, 0.f};
    size_t base = (size_t)idx * NCh * NS;
    for (int ch = 0; ch < NCh; ch++) {
        size_t o = base + ch * NS;
#pragma unroll
        for (int n = 0; n < NS; n++) {
            float He = Hc[o + n];
            float Pv = P[o + n];
            Hc[o + n] = h[n];
            h[n] = fmaf(Pv, h[n], He);
        }
    }
}

__global__ void scan3_b(const __nv_bfloat16* __restrict__ dt,
                        const __nv_bfloat16* __restrict__ u,
                        const float* __restrict__ dbl,
                        const float* __restrict__ Hc, ScanArgs sa,
                        const __nv_bfloat16* __restrict__ uz,
                        __nv_bfloat16* __restrict__ yz)
{
    const int s = blockIdx.y >> 1;
    const int b = blockIdx.y & 1;
    dt += (size_t)s * Mrows * Cd;
    u  += (size_t)s * Mrows * Cd;
    uz += (size_t)s * Mrows * TWOD;
    yz += (size_t)s * Mrows * Cd;
    Hc += (size_t)s * Bb * Cd * NCh * NS;
    const float* dbl_self  = dbl + (size_t)s * Mrows * DBLS;
    const float* dbl_other = dbl + (size_t)(1 - s) * Mrows * DBLS;
    const float* Alog = sa.Alog[s];
    const float* Dskip = sa.Dsk[s];

    int d  = blockIdx.z * 256 + threadIdx.x;
    int ch = blockIdx.x;
    float An[NS];
#pragma unroll
    for (int n = 0; n < NS; n++) An[n] = -__expf(Alog[d * NS + n]);
    float h[NS];
    size_t ho = (((size_t)(b * Cd + d)) * NCh + ch) * NS;
#pragma unroll
    for (int n = 0; n < NS; n++) h[n] = Hc[ho + n];
    float dsk = Dskip[d];
    int l0 = ch * LCh;
    for (int l = l0; l < l0 + LCh; l++) {
        int r = b * Lh + l;
        float dtv = __bfloat162float(dt[(size_t)r * Cd + d]);
        float uv  = __bfloat162float(u [(size_t)r * Cd + d]);
        float du  = dtv * uv;
        const float* Bp = dbl_self  + (size_t)r * DBLS + RK;
        const float* Cp = dbl_other + (size_t)r * DBLS + RK + NS;
        float y = uv * dsk;
#pragma unroll
        for (int n = 0; n < NS; n++) {
            float dA = __expf(dtv * An[n]);
            h[n] = fmaf(dA, h[n], du * Bp[n]);
            y = fmaf(h[n], Cp[n], y);
        }
        float z  = __bfloat162float(uz[(size_t)r * TWOD + Cd + d]);
        float sz = z / (1.f + __expf(-z));
        yz[(size_t)r * Cd + d] = __float2bfloat16(y * sz);
    }
}

// ---------------------------------------------------------------------------
// Launch (my idx 4 = in_proj stream 1 -> global ncu window idx 5)
// ---------------------------------------------------------------------------
extern "C" void kernel_launch(void* const* d_in, const int* in_sizes, int n_in,
                              void* d_out, int out_size)
{
    (void)in_sizes; (void)n_in; (void)out_size;

    float *xt, *mean, *rstd, *dbl, *P, *Hc;
    __nv_bfloat16 *xnb, *uzb, *ub, *dtrb, *dtb, *yzb, *wint, *woutt, *wxpt, *wdtt;
    cudaGetSymbolAddress((void**)&xt,    g_xt);
    cudaGetSymbolAddress((void**)&xnb,   g_xnb);
    cudaGetSymbolAddress((void**)&mean,  g_mean);
    cudaGetSymbolAddress((void**)&rstd,  g_rstd);
    cudaGetSymbolAddress((void**)&uzb,   g_uzb);
    cudaGetSymbolAddress((void**)&ub,    g_ub);
    cudaGetSymbolAddress((void**)&dbl,   g_dbl);
    cudaGetSymbolAddress((void**)&dtrb,  g_dtrb);
    cudaGetSymbolAddress((void**)&dtb,   g_dtb);
    cudaGetSymbolAddress((void**)&yzb,   g_yzb);
    cudaGetSymbolAddress((void**)&P,     g_P);
    cudaGetSymbolAddress((void**)&Hc,    g_Hc);
    cudaGetSymbolAddress((void**)&wint,  g_wint);
    cudaGetSymbolAddress((void**)&woutt, g_woutt);
    cudaGetSymbolAddress((void**)&wxpt,  g_wxpt);
    cudaGetSymbolAddress((void**)&wdtt,  g_wdtt);

    const size_t SC  = (size_t)Mrows * Cd;
    const size_t SUZ = (size_t)Mrows * TWOD;

    const float* Xin[2] = { (const float*)d_in[0], (const float*)d_in[1] };
    const float *lng[2], *lnb[2], *Win[2], *Wcv[2], *bcv[2], *Wxp[2],
                *Wdt[2], *bdt[2], *Alog[2], *Dsk[2], *Wout[2];
    for (int s = 0; s < 2; s++) {
        int o = 2 + s * 11;
        lng[s]  = (const float*)d_in[o + 0];
        lnb[s]  = (const float*)d_in[o + 1];
        Win[s]  = (const float*)d_in[o + 2];
        Wcv[s]  = (const float*)d_in[o + 3];
        bcv[s]  = (const float*)d_in[o + 4];
        Wxp[s]  = (const float*)d_in[o + 5];
        Wdt[s]  = (const float*)d_in[o + 6];
        bdt[s]  = (const float*)d_in[o + 7];
        Alog[s] = (const float*)d_in[o + 8];
        Dsk[s]  = (const float*)d_in[o + 9];
        Wout[s] = (const float*)d_in[o + 10];
    }

    // ---- launch 0: weight prep ----
    WtArgs wa;
    for (int s = 0; s < 2; s++) {
        wa.W[s * 4 + 0] = Win[s];  wa.Wt[s * 4 + 0] = wint  + s * (size_t)TWOD * Cd;
        wa.W[s * 4 + 1] = Wout[s]; wa.Wt[s * 4 + 1] = woutt + s * (size_t)Cd * Cd;
        wa.W[s * 4 + 2] = Wxp[s];  wa.Wt[s * 4 + 2] = wxpt  + s * (size_t)64 * Cd;
        wa.W[s * 4 + 3] = Wdt[s];  wa.Wt[s * 4 + 3] = wdtt  + s * (size_t)Cd * 64;
    }
    wt_all_k<<<dim3(Cd / 32, TWOD / 32, 8), dim3(32, 8)>>>(wa);

    // ---- launch 1: LN stats (both streams) ----
    ln_stats_b<<<dim3(Mrows / 32, 2), 256>>>(Xin[0], Xin[1], mean, rstd);

    // ---- launch 2: transpose + norm (both streams) ----
    TnArgs ta;
    for (int s = 0; s < 2; s++) { ta.x[s] = Xin[s]; ta.g[s] = lng[s]; ta.lb[s] = lnb[s]; }
    tn_b<<<dim3(Lh / 32, Cd / 32, 2 * Bb), dim3(32, 8)>>>(ta, mean, rstd, xt, xnb);

    // ---- launches 3,4: in_proj per stream, bf16 output (idx 4 -> ncu) ----
    for (int s = 0; s < 2; s++) {
        GemmAux ipa = { { nullptr, nullptr }, { uzb + s * SUZ, nullptr } };
        hgemm_k<4><<<dim3(TWOD / 64, Mrows / 64, 1), 128>>>(
            xnb + s * SC, Cd, 0, wint + s * (size_t)TWOD * Cd, 0,
            (float*)nullptr, TWOD, 0, Cd, ipa);
    }

    // ---- launch 5: conv + silu (both) ----
    ConvArgs ca = { { Wcv[0], Wcv[1] }, { bcv[0], bcv[1] } };
    conv_silu_b<<<dim3(((Mrows / 4) * Cd + 255) / 256, 2), 256>>>(uzb, ca, ub);

    // ---- launch 6: x_proj (both) ----
    GemmAux xpa = { { nullptr, nullptr }, { dtrb, dtrb + (size_t)Mrows * 64 } };
    hgemm_k<1><<<dim3(1, Mrows / 64, 2), 128>>>(
        ub, Cd, SC, wxpt, (size_t)64 * Cd,
        dbl, DBLS, (size_t)Mrows * DBLS, Cd, xpa);

    // ---- launch 7: dt proj + softplus -> bf16 (both) ----
    GemmAux dta = { { bdt[0], bdt[1] }, { dtb, dtb + SC } };
    hgemm_k<2><<<dim3(Cd / 64, Mrows / 64, 2), 128>>>(
        dtrb, 64, (size_t)Mrows * 64, wdtt, (size_t)Cd * 64,
        (float*)nullptr, Cd, 0, 64, dta);

    // ---- launches 8-10: selective scans (both) ----
    ScanArgs sa = { { Alog[0], Alog[1] }, { Dsk[0], Dsk[1] } };
    scan1_b<<<dim3(NCh, 2 * Bb, Cd / 256), 256>>>(dtb, ub, dbl, sa, P, Hc);
    scan2_b<<<(2 * Bb * Cd + 255) / 256, 256>>>(P, Hc);
    scan3_b<<<dim3(NCh, 2 * Bb, Cd / 256), 256>>>(dtb, ub, dbl, Hc, sa, uzb, yzb);

    // ---- launch 11: out_proj + residual (both) ----
    GemmAux opa = { { xt, xt + SC }, { nullptr, nullptr } };
    hgemm_k<3><<<dim3(Cd / 64, Mrows / 64, 2), 128>>>(
        yzb, Cd, SC, woutt, (size_t)Cd * Cd,
        (float*)d_out, Cd, SC, Cd, opa);
}